// round 2
// baseline (speedup 1.0000x reference)
#include <cuda_runtime.h>
#include <math.h>

// Problem constants
#define B_  8192
#define N_  32
#define D_  128
#define M_  384
#define H_  2
#define DK_ 192

// ---------------------------------------------------------------------------
// Static device scratch (allocation-free rule: __device__ globals)
// ---------------------------------------------------------------------------
__device__ __align__(16) float g_Tq[2 * 256 * 192];           // w_q transposed per head (used cols only)
__device__ __align__(16) float g_Tk[2 * 384 * 192];           // w_k transposed per head
__device__ __align__(16) float g_Tv[2 * 384 * 192];           // w_v transposed per head
__device__ __align__(16) float g_Ahat[768 * 256];             // folded q-projection (incl. 1/sqrt(DK))
__device__ __align__(16) float g_Bhat[384 * 768];             // folded fc @ w_v
__device__ __align__(16) float g_Qt[(size_t)B_ * 768];        // q-tilde per batch
__device__ __align__(16) float g_C[(size_t)B_ * 768];         // attn-weighted key sums (per head)
__device__ __align__(16) float g_Y[(size_t)B_ * 384];         // fc output -> layernormed in place
__device__ __align__(16) float g_H[(size_t)B_ * 128];         // merge hidden

// ---------------------------------------------------------------------------
// Tiled transpose of per-head weight slices: dst[(h*cols + c)*192 + d] =
//   src[(h*192 + d)*384 + map(c)],  map(c) = c < split ? c : c + shift
// (w_q uses split=128, shift=128 to drop the always-zero middle 128 columns)
// ---------------------------------------------------------------------------
__global__ void transpose_head(const float* __restrict__ src, float* __restrict__ dst,
                               int cols, int split, int shift)
{
    __shared__ float tile[32][33];
    const int h  = blockIdx.z;
    const int c0 = blockIdx.x * 32;
    const int d0 = blockIdx.y * 32;
    const int tx = threadIdx.x, ty = threadIdx.y;

#pragma unroll
    for (int r = 0; r < 4; r++) {
        int d = d0 + ty + r * 8;
        int c = c0 + tx;
        int cm = (c < split) ? c : c + shift;
        tile[ty + r * 8][tx] = src[(size_t)(h * 192 + d) * 384 + cm];
    }
    __syncthreads();
#pragma unroll
    for (int r = 0; r < 4; r++) {
        int c = c0 + ty + r * 8;
        int d = d0 + tx;
        dst[(size_t)(h * cols + c) * 192 + d] = tile[tx][ty + r * 8];
    }
}

// ---------------------------------------------------------------------------
// Generic fp32 NT-SGEMM: out[m,n] = scale * sum_k A[m,k]*W[n,k] (+bias[n]) (relu)
// A can be split along K into two sources (A0 for k<splitK, A1 for the rest).
// BM=128, BN=64, BK=16, 256 threads, 8x4 micro-tile.
// All M % 128 == 0, N % 64 == 0, K % 16 == 0, splitK % 16 == 0 in this problem.
// ---------------------------------------------------------------------------
__global__ __launch_bounds__(256) void sgemm_nt(
    const float* __restrict__ A0, const float* __restrict__ A1, int splitK,
    int lda0, int lda1,
    const float* __restrict__ W, int ldw,
    const float* __restrict__ bias,
    float* __restrict__ out, int ldc,
    int K, float scale, int do_relu)
{
    __shared__ float As[16][128];
    __shared__ float Ws[16][64];

    const int tid = threadIdx.x;
    const int bm  = blockIdx.y * 128;
    const int bn  = blockIdx.x * 64;

    float acc[8][4];
#pragma unroll
    for (int i = 0; i < 8; i++)
#pragma unroll
        for (int j = 0; j < 4; j++) acc[i][j] = 0.f;

    const int trow = (tid >> 4) * 8;   // 0..120
    const int tcol = (tid & 15) * 4;   // 0..60

    for (int k0 = 0; k0 < K; k0 += 16) {
        // Load A tile: 128x16 = 512 float4, 2 per thread
#pragma unroll
        for (int l = 0; l < 2; l++) {
            int lin = tid + l * 256;
            int r   = lin >> 2;
            int kk  = (lin & 3) << 2;
            int gk  = k0 + kk;
            int gm  = bm + r;
            float4 v;
            if (gk < splitK)
                v = *(const float4*)(A0 + (size_t)gm * lda0 + gk);
            else
                v = *(const float4*)(A1 + (size_t)gm * lda1 + (gk - splitK));
            As[kk + 0][r] = v.x; As[kk + 1][r] = v.y;
            As[kk + 2][r] = v.z; As[kk + 3][r] = v.w;
        }
        // Load W tile: 64x16 = 256 float4, 1 per thread
        {
            int r  = tid >> 2;
            int kk = (tid & 3) << 2;
            float4 v = *(const float4*)(W + (size_t)(bn + r) * ldw + k0 + kk);
            Ws[kk + 0][r] = v.x; Ws[kk + 1][r] = v.y;
            Ws[kk + 2][r] = v.z; Ws[kk + 3][r] = v.w;
        }
        __syncthreads();

#pragma unroll
        for (int kk = 0; kk < 16; kk++) {
            float a[8], b[4];
#pragma unroll
            for (int i = 0; i < 8; i++) a[i] = As[kk][trow + i];
#pragma unroll
            for (int j = 0; j < 4; j++) b[j] = Ws[kk][tcol + j];
#pragma unroll
            for (int i = 0; i < 8; i++)
#pragma unroll
                for (int j = 0; j < 4; j++) acc[i][j] += a[i] * b[j];
        }
        __syncthreads();
    }

#pragma unroll
    for (int j = 0; j < 4; j++) {
        float bj = bias ? bias[bn + tcol + j] : 0.f;
#pragma unroll
        for (int i = 0; i < 8; i++) {
            float v = acc[i][j] * scale + bj;
            if (do_relu) v = fmaxf(v, 0.f);
            out[(size_t)(bm + trow + i) * ldc + bn + tcol + j] = v;
        }
    }
}

// ---------------------------------------------------------------------------
// Fused attention: per batch b (one CTA, 256 threads):
//   k[n] = [seq, seq_e, seq_t][b,n]  (32 x 384, held in smem w/ stride 388)
//   scores[h,n] = qtilde[b,h] . k[n]      (scale already folded into Ahat)
//   masked softmax over n; write attn_w output
//   C[b, h*384+j] = sum_n attn[h,n] * k[n][j]
// ---------------------------------------------------------------------------
#define KSTRIDE 388  // 384 + 4 pad: kills 8-way bank conflicts in score dots

__global__ __launch_bounds__(256) void attn_kernel(
    const float* __restrict__ Qt,
    const float* __restrict__ seq,
    const float* __restrict__ seq_e,
    const float* __restrict__ seq_t,
    const int*   __restrict__ mask,
    float* __restrict__ Cbuf,
    float* __restrict__ attn_out)
{
    extern __shared__ float sm[];
    float* kbuf = sm;                      // 32 * 388
    float* qs   = sm + 32 * KSTRIDE;       // 768
    float* sc   = qs + 768;                // 64
    float* at   = sc + 64;                 // 64

    const int b   = blockIdx.x;
    const int tid = threadIdx.x;

    for (int i = tid; i < 768; i += 256)
        qs[i] = Qt[(size_t)b * 768 + i];

    // Load k tile: 32 rows x 384 floats, as 3072 float4s
    for (int i4 = tid; i4 < 3072; i4 += 256) {
        int n   = i4 / 96;
        int jq  = i4 - n * 96;            // float4 index in [0,96)
        int seg = jq >> 5;                // 0:seq 1:seq_e 2:seq_t
        int dq  = jq & 31;
        const float* p = (seg == 0) ? seq : ((seg == 1) ? seq_e : seq_t);
        float4 v = *(const float4*)(p + ((size_t)(b * 32 + n)) * 128 + dq * 4);
        *(float4*)(kbuf + n * KSTRIDE + jq * 4) = v;
    }
    __syncthreads();

    // Scores: quad of threads per (h,n) pair; 64 pairs
    {
        int g  = tid >> 2;
        int ql = tid & 3;
        int h  = g >> 5;
        int n  = g & 31;
        const float* kr = kbuf + n * KSTRIDE;
        const float* qr = qs + h * 384;
        float s = 0.f;
#pragma unroll 8
        for (int j = ql; j < 384; j += 4)
            s += kr[j] * qr[j];
        s += __shfl_down_sync(0xffffffffu, s, 2);
        s += __shfl_down_sync(0xffffffffu, s, 1);
        if (ql == 0) {
            if (mask[b * 32 + n] != 0) s = -1e10f;
            sc[g] = s;
        }
    }
    __syncthreads();

    // Softmax: warp 0 -> head 0, warp 1 -> head 1 (lane = n)
    const int wid  = tid >> 5;
    const int lane = tid & 31;
    if (wid < 2) {
        float s = sc[wid * 32 + lane];
        float m = s;
#pragma unroll
        for (int o = 16; o > 0; o >>= 1)
            m = fmaxf(m, __shfl_xor_sync(0xffffffffu, m, o));
        float e = expf(s - m);
        float sum = e;
#pragma unroll
        for (int o = 16; o > 0; o >>= 1)
            sum += __shfl_xor_sync(0xffffffffu, sum, o);
        float p = e / sum;
        at[wid * 32 + lane] = p;
        attn_out[((size_t)wid * B_ + b) * 32 + lane] = p;  // attn_w[(h*B+b), n]
    }
    __syncthreads();

    // C[b, h*384+j] = sum_n attn[h,n] * k[n][j]
    for (int c = tid; c < 768; c += 256) {
        int h = (c >= 384) ? 1 : 0;
        int j = c - h * 384;
        const float* av = at + h * 32;
        float accv = 0.f;
#pragma unroll
        for (int n = 0; n < 32; n++)
            accv += av[n] * kbuf[n * KSTRIDE + j];
        Cbuf[(size_t)b * 768 + c] = accv;
    }
}

// ---------------------------------------------------------------------------
// In-place LayerNorm over rows of 384 (one warp per row)
// ---------------------------------------------------------------------------
__global__ __launch_bounds__(256) void ln_kernel(
    float* __restrict__ Y,
    const float* __restrict__ ln_g,
    const float* __restrict__ ln_b)
{
    const int row  = blockIdx.x * 8 + (threadIdx.x >> 5);
    const int lane = threadIdx.x & 31;
    float* y = Y + (size_t)row * 384;

    float v[12];
    float s = 0.f;
#pragma unroll
    for (int i = 0; i < 12; i++) { v[i] = y[lane + i * 32]; s += v[i]; }
#pragma unroll
    for (int o = 16; o > 0; o >>= 1) s += __shfl_xor_sync(0xffffffffu, s, o);
    float mu = s * (1.f / 384.f);

    float q = 0.f;
#pragma unroll
    for (int i = 0; i < 12; i++) { float d = v[i] - mu; q += d * d; }
#pragma unroll
    for (int o = 16; o > 0; o >>= 1) q += __shfl_xor_sync(0xffffffffu, q, o);
    float inv = rsqrtf(q * (1.f / 384.f) + 1e-5f);

#pragma unroll
    for (int i = 0; i < 12; i++) {
        int c = lane + i * 32;
        y[c] = (v[i] - mu) * inv * ln_g[c] + ln_b[c];
    }
}

// ---------------------------------------------------------------------------
// Launch
// ---------------------------------------------------------------------------
extern "C" void kernel_launch(void* const* d_in, const int* in_sizes, int n_in,
                              void* d_out, int out_size)
{
    const float* src   = (const float*)d_in[0];
    const float* src_t = (const float*)d_in[1];
    const float* seq   = (const float*)d_in[2];
    const float* seq_t = (const float*)d_in[3];
    const float* seq_e = (const float*)d_in[4];
    /* d_in[5] = time_diff (unused) */
    const int*   mask  = (const int*)d_in[6];   // nonzero word == masked (covers int32 & f32 encodings)
    const float* w_q   = (const float*)d_in[7];
    const float* w_k   = (const float*)d_in[8];
    const float* w_v   = (const float*)d_in[9];
    const float* fc_w  = (const float*)d_in[10];
    const float* fc_b  = (const float*)d_in[11];
    const float* ln_g  = (const float*)d_in[12];
    const float* ln_b  = (const float*)d_in[13];
    const float* mg_w1 = (const float*)d_in[14];
    const float* mg_b1 = (const float*)d_in[15];
    const float* mg_w2 = (const float*)d_in[16];
    const float* mg_b2 = (const float*)d_in[17];
    float* out = (float*)d_out;
    float* merged_out = out;                       // (8192, 128)
    float* attn_out   = out + (size_t)B_ * D_;     // (2*8192, 32)

    float *Tq, *Tk, *Tv, *Ahat, *Bhat, *Qt, *Cb, *Y, *Hb;
    cudaGetSymbolAddress((void**)&Tq,   g_Tq);
    cudaGetSymbolAddress((void**)&Tk,   g_Tk);
    cudaGetSymbolAddress((void**)&Tv,   g_Tv);
    cudaGetSymbolAddress((void**)&Ahat, g_Ahat);
    cudaGetSymbolAddress((void**)&Bhat, g_Bhat);
    cudaGetSymbolAddress((void**)&Qt,   g_Qt);
    cudaGetSymbolAddress((void**)&Cb,   g_C);
    cudaGetSymbolAddress((void**)&Y,    g_Y);
    cudaGetSymbolAddress((void**)&Hb,   g_H);

    const int ATTN_SMEM = (32 * KSTRIDE + 768 + 64 + 64) * (int)sizeof(float); // 53248
    cudaFuncSetAttribute(attn_kernel, cudaFuncAttributeMaxDynamicSharedMemorySize, ATTN_SMEM);

    dim3 tb(32, 8);
    // Per-head transposed weight slices (d-major rows)
    transpose_head<<<dim3(256 / 32, 6, 2), tb>>>(w_q, Tq, 256, 128, 128);
    transpose_head<<<dim3(384 / 32, 6, 2), tb>>>(w_k, Tk, 384, 384, 0);
    transpose_head<<<dim3(384 / 32, 6, 2), tb>>>(w_v, Tv, 384, 384, 0);

    const float invs = (float)(1.0 / sqrt((double)DK_));
    const int BIGK = 1 << 30;

    for (int h = 0; h < 2; h++) {
        // Ahat[h*384+j, i'] = invs * sum_d Tk[h][j][d] * Tq[h][i'][d]
        sgemm_nt<<<dim3(256 / 64, 384 / 128), 256>>>(
            Tk + (size_t)h * 384 * 192, Tk, BIGK, 192, 192,
            Tq + (size_t)h * 256 * 192, 192, nullptr,
            Ahat + (size_t)h * 384 * 256, 256, 192, invs, 0);
        // Bhat[i, h*384+j] = sum_t fc_w[i, h*192+t] * Tv[h][j][t]
        sgemm_nt<<<dim3(384 / 64, 384 / 128), 256>>>(
            fc_w + h * 192, fc_w, BIGK, 384, 384,
            Tv + (size_t)h * 384 * 192, 192, nullptr,
            Bhat + (size_t)h * 384, 768, 192, 1.f, 0);
    }

    // Qt = [src | src_t] @ Ahat^T   (8192 x 768)
    sgemm_nt<<<dim3(768 / 64, B_ / 128), 256>>>(
        src, src_t, 128, 128, 128,
        Ahat, 256, nullptr, Qt, 768, 256, 1.f, 0);

    // Fused attention -> Cb and attn_w output
    attn_kernel<<<B_, 256, ATTN_SMEM>>>(Qt, seq, seq_e, seq_t, mask, Cb, attn_out);

    // Y = Cb @ Bhat^T + fc_b   (8192 x 384)
    sgemm_nt<<<dim3(384 / 64, B_ / 128), 256>>>(
        Cb, Cb, BIGK, 768, 768,
        Bhat, 768, fc_b, Y, 384, 768, 1.f, 0);

    // LayerNorm in place
    ln_kernel<<<B_ / 8, 256>>>(Y, ln_g, ln_b);

    // Hb = relu([Y | src] @ mg_w1^T + mg_b1)   (8192 x 128)
    sgemm_nt<<<dim3(128 / 64, B_ / 128), 256>>>(
        Y, src, 384, 384, 128,
        mg_w1, 512, mg_b1, Hb, 128, 512, 1.f, 1);

    // merged = Hb @ mg_w2^T + mg_b2   (8192 x 128)
    sgemm_nt<<<dim3(128 / 64, B_ / 128), 256>>>(
        Hb, Hb, BIGK, 128, 128,
        mg_w2, 128, mg_b2, merged_out, 128, 128, 1.f, 0);

    (void)in_sizes; (void)n_in; (void)out_size; (void)seq_t;
}

// round 4
// speedup vs baseline: 1.6855x; 1.6855x over previous
#include <cuda_runtime.h>
#include <cuda_bf16.h>
#include <math.h>
#include <stdint.h>

// Problem constants
#define B_  8192
#define N_  32
#define D_  128
#define M_  384
#define H_  2
#define DK_ 192
#define BIGK (1 << 30)

// ---------------------------------------------------------------------------
// Static device scratch
// ---------------------------------------------------------------------------
__device__ __align__(16) float g_Tq[2 * 256 * 192];
__device__ __align__(16) float g_Tk[2 * 384 * 192];
__device__ __align__(16) float g_Tv[2 * 384 * 192];
__device__ __align__(16) float g_Ahat[768 * 256];
__device__ __align__(16) float g_Bhat[384 * 768];
__device__ __align__(16) float g_Qt[(size_t)B_ * 768];
__device__ __align__(16) float g_C[(size_t)B_ * 768];
__device__ __align__(16) float g_Y[(size_t)B_ * 384];
__device__ __align__(16) float g_H[(size_t)B_ * 128];

// ---------------------------------------------------------------------------
// MMA helpers (baseline PTX: valid at compute_103, no 'a' features)
// ---------------------------------------------------------------------------
__device__ __forceinline__ uint32_t smem_u32(const void* p) {
    uint32_t a;
    asm("{ .reg .u64 t; cvta.to.shared.u64 t, %1; cvt.u32.u64 %0, t; }"
        : "=r"(a) : "l"(p));
    return a;
}

__device__ __forceinline__ void mma_bf16(float* d, const uint32_t* a, const uint32_t* b) {
    asm volatile(
        "mma.sync.aligned.m16n8k16.row.col.f32.bf16.bf16.f32 "
        "{%0,%1,%2,%3}, {%4,%5,%6,%7}, {%8,%9}, {%0,%1,%2,%3};"
        : "+f"(d[0]), "+f"(d[1]), "+f"(d[2]), "+f"(d[3])
        : "r"(a[0]), "r"(a[1]), "r"(a[2]), "r"(a[3]), "r"(b[0]), "r"(b[1]));
}

__device__ __forceinline__ void ldmx4(uint32_t* r, uint32_t addr) {
    asm volatile("ldmatrix.sync.aligned.m8n8.x4.shared.b16 {%0,%1,%2,%3}, [%4];"
        : "=r"(r[0]), "=r"(r[1]), "=r"(r[2]), "=r"(r[3]) : "r"(addr));
}

// fp32 -> bf16 hi/lo split, two elements packed per word
__device__ __forceinline__ void bsplit(float a, float b, uint32_t& hi, uint32_t& lo) {
    __nv_bfloat16 ha = __float2bfloat16_rn(a), hb = __float2bfloat16_rn(b);
    __nv_bfloat16 la = __float2bfloat16_rn(a - __bfloat162float(ha));
    __nv_bfloat16 lb = __float2bfloat16_rn(b - __bfloat162float(hb));
    hi = ((uint32_t)__bfloat16_as_ushort(hb) << 16) | (uint32_t)__bfloat16_as_ushort(ha);
    lo = ((uint32_t)__bfloat16_as_ushort(lb) << 16) | (uint32_t)__bfloat16_as_ushort(la);
}

// ---------------------------------------------------------------------------
// bf16x3 tensor-core GEMM via mma.sync:
//   out[m,n] = scale * sum_k A[m,k]*W[n,k] (+bias[n]) (relu)
// A split along K (A0 for k<splitK, else A1). BM=128, BN=64, BK=32.
// Requires K%32==0, splitK%32==0 (or huge), M%128==0, N%64==0.
// blockIdx.z batching via element strides sA/sW/sO.
// Stage layout (24576 B): A_hi[128x32] | A_lo | B_hi[64x32] | B_lo
// 16B-chunk swizzle within 64B rows: chunk' = chunk ^ ((row>>1)&3)
// ---------------------------------------------------------------------------
__global__ __launch_bounds__(256, 2) void mma_gemm(
    const float* __restrict__ A0, const float* __restrict__ A1, int splitK,
    int lda0, int lda1,
    const float* __restrict__ W, int ldw,
    const float* __restrict__ bias,
    float* __restrict__ out, int ldc,
    int K, float scale, int do_relu,
    size_t sA, size_t sW, size_t sO)
{
    __shared__ __align__(1024) char smbuf[2][24576];

    const int tid  = threadIdx.x;
    const int lane = tid & 31, wid = tid >> 5;
    const int bm = blockIdx.y * 128, bn = blockIdx.x * 64;
    const int z  = blockIdx.z;
    A0 += sA * z; A1 += sA * z; W += sW * z; out += sO * z;

    const int mw = (wid >> 1) * 32;   // warp m-origin (4 warps in m)
    const int nw = (wid & 1) * 32;    // warp n-origin (2 warps in n)

    const int lt = lane >> 3;         // ldmatrix tile index 0..3
    const int lr = lane & 7;          // row within tile

    float acc[2][4][4];
#pragma unroll
    for (int i = 0; i < 2; i++)
#pragma unroll
        for (int j = 0; j < 4; j++)
#pragma unroll
            for (int q = 0; q < 4; q++) acc[i][j][q] = 0.f;

    const uint32_t smA = smem_u32(&smbuf[0][0]);
    const int nch = K >> 5;

    float4 ra[4], rb[2];

    auto LOAD = [&](int c) {
        const int k0 = c << 5;
#pragma unroll
        for (int i = 0; i < 4; i++) {
            int lin = tid + (i << 8);
            int r = lin >> 3, q = lin & 7;
            int gk = k0 + (q << 2);
            const float* p = (gk < splitK)
                ? (A0 + (size_t)(bm + r) * lda0 + gk)
                : (A1 + (size_t)(bm + r) * lda1 + (gk - splitK));
            ra[i] = *(const float4*)p;
        }
#pragma unroll
        for (int i = 0; i < 2; i++) {
            int lin = tid + (i << 8);
            int r = lin >> 3, q = lin & 7;
            rb[i] = *(const float4*)(W + (size_t)(bn + r) * ldw + k0 + (q << 2));
        }
    };

    auto STORE = [&](int s) {
        char* st = smbuf[s];
#pragma unroll
        for (int i = 0; i < 4; i++) {
            int lin = tid + (i << 8);
            int r = lin >> 3, q = lin & 7;
            uint32_t h0, l0, h1, l1;
            bsplit(ra[i].x, ra[i].y, h0, l0);
            bsplit(ra[i].z, ra[i].w, h1, l1);
            uint32_t off = (uint32_t)(r * 64 + (((q >> 1) ^ ((r >> 1) & 3)) << 4) + ((q & 1) << 3));
            *(uint2*)(st + off)        = make_uint2(h0, h1);
            *(uint2*)(st + 8192 + off) = make_uint2(l0, l1);
        }
#pragma unroll
        for (int i = 0; i < 2; i++) {
            int lin = tid + (i << 8);
            int r = lin >> 3, q = lin & 7;
            uint32_t h0, l0, h1, l1;
            bsplit(rb[i].x, rb[i].y, h0, l0);
            bsplit(rb[i].z, rb[i].w, h1, l1);
            uint32_t off = (uint32_t)(r * 64 + (((q >> 1) ^ ((r >> 1) & 3)) << 4) + ((q & 1) << 3));
            *(uint2*)(st + 16384 + off) = make_uint2(h0, h1);
            *(uint2*)(st + 20480 + off) = make_uint2(l0, l1);
        }
    };

    auto COMPUTE = [&](int s) {
        const uint32_t base = smA + (uint32_t)s * 24576u;
#pragma unroll
        for (int ks = 0; ks < 2; ks++) {
            uint32_t Ah[2][4], Al[2][4], Bh[4][2], Bl[4][2];
#pragma unroll
            for (int mt = 0; mt < 2; mt++) {
                int m  = mw + mt * 16 + ((lt & 1) << 3) + lr;
                int cc = ks * 2 + (lt >> 1);
                uint32_t off = (uint32_t)(m * 64 + ((cc ^ ((m >> 1) & 3)) << 4));
                ldmx4(Ah[mt], base + off);
                ldmx4(Al[mt], base + 8192u + off);
            }
#pragma unroll
            for (int p = 0; p < 2; p++) {
                int n  = nw + ((2 * p + (lt >> 1)) << 3) + lr;
                int cc = ks * 2 + (lt & 1);
                uint32_t off = (uint32_t)(n * 64 + ((cc ^ ((n >> 1) & 3)) << 4));
                uint32_t t[4];
                ldmx4(t, base + 16384u + off);
                Bh[2 * p][0] = t[0]; Bh[2 * p][1] = t[1];
                Bh[2 * p + 1][0] = t[2]; Bh[2 * p + 1][1] = t[3];
                ldmx4(t, base + 20480u + off);
                Bl[2 * p][0] = t[0]; Bl[2 * p][1] = t[1];
                Bl[2 * p + 1][0] = t[2]; Bl[2 * p + 1][1] = t[3];
            }
#pragma unroll
            for (int mt = 0; mt < 2; mt++)
#pragma unroll
                for (int nt = 0; nt < 4; nt++) {
                    mma_bf16(acc[mt][nt], Ah[mt], Bh[nt]);
                    mma_bf16(acc[mt][nt], Ah[mt], Bl[nt]);
                    mma_bf16(acc[mt][nt], Al[mt], Bh[nt]);
                }
        }
    };

    LOAD(0); STORE(0); __syncthreads();
    for (int c = 0; c < nch; c++) {
        if (c + 1 < nch) LOAD(c + 1);
        COMPUTE(c & 1);
        if (c + 1 < nch) STORE((c + 1) & 1);
        __syncthreads();
    }

    // Epilogue: fragment -> global (c0,c1 @ row, c2,c3 @ row+8)
    const int er = lane >> 2, ec = (lane & 3) << 1;
#pragma unroll
    for (int mt = 0; mt < 2; mt++)
#pragma unroll
        for (int nt = 0; nt < 4; nt++) {
            int row = bm + mw + mt * 16 + er;
            int col = bn + nw + nt * 8 + ec;
            float b0 = bias ? bias[col] : 0.f;
            float b1 = bias ? bias[col + 1] : 0.f;
            float v0 = acc[mt][nt][0] * scale + b0;
            float v1 = acc[mt][nt][1] * scale + b1;
            float v2 = acc[mt][nt][2] * scale + b0;
            float v3 = acc[mt][nt][3] * scale + b1;
            if (do_relu) {
                v0 = fmaxf(v0, 0.f); v1 = fmaxf(v1, 0.f);
                v2 = fmaxf(v2, 0.f); v3 = fmaxf(v3, 0.f);
            }
            *(float2*)(out + (size_t)row * ldc + col)       = make_float2(v0, v1);
            *(float2*)(out + (size_t)(row + 8) * ldc + col) = make_float2(v2, v3);
        }
}

// ---------------------------------------------------------------------------
// Tiled per-head weight transpose
// ---------------------------------------------------------------------------
__global__ void transpose_head(const float* __restrict__ src, float* __restrict__ dst,
                               int cols, int split, int shift)
{
    __shared__ float tile[32][33];
    const int h  = blockIdx.z;
    const int c0 = blockIdx.x * 32;
    const int d0 = blockIdx.y * 32;
    const int tx = threadIdx.x, ty = threadIdx.y;

#pragma unroll
    for (int r = 0; r < 4; r++) {
        int d = d0 + ty + r * 8;
        int c = c0 + tx;
        int cm = (c < split) ? c : c + shift;
        tile[ty + r * 8][tx] = src[(size_t)(h * 192 + d) * 384 + cm];
    }
    __syncthreads();
#pragma unroll
    for (int r = 0; r < 4; r++) {
        int c = c0 + ty + r * 8;
        int d = d0 + tx;
        dst[(size_t)(h * cols + c) * 192 + d] = tile[tx][ty + r * 8];
    }
}

// ---------------------------------------------------------------------------
// Fused attention (fp32, DRAM-bound)
// ---------------------------------------------------------------------------
#define KSTRIDE 388

__global__ __launch_bounds__(256) void attn_kernel(
    const float* __restrict__ Qt,
    const float* __restrict__ seq,
    const float* __restrict__ seq_e,
    const float* __restrict__ seq_t,
    const int*   __restrict__ mask,
    float* __restrict__ Cbuf,
    float* __restrict__ attn_out)
{
    extern __shared__ __align__(1024) char dynsm[];
    float* sm   = (float*)dynsm;
    float* kbuf = sm;
    float* qs   = sm + 32 * KSTRIDE;
    float* sc   = qs + 768;
    float* at   = sc + 64;

    const int b   = blockIdx.x;
    const int tid = threadIdx.x;

    for (int i = tid; i < 768; i += 256)
        qs[i] = Qt[(size_t)b * 768 + i];

    for (int i4 = tid; i4 < 3072; i4 += 256) {
        int n   = i4 / 96;
        int jq  = i4 - n * 96;
        int seg = jq >> 5;
        int dq  = jq & 31;
        const float* p = (seg == 0) ? seq : ((seg == 1) ? seq_e : seq_t);
        float4 v = *(const float4*)(p + ((size_t)(b * 32 + n)) * 128 + dq * 4);
        *(float4*)(kbuf + n * KSTRIDE + jq * 4) = v;
    }
    __syncthreads();

    {
        int g  = tid >> 2;
        int ql = tid & 3;
        int h  = g >> 5;
        int n  = g & 31;
        const float* kr = kbuf + n * KSTRIDE;
        const float* qr = qs + h * 384;
        float s = 0.f;
#pragma unroll 8
        for (int j = ql; j < 384; j += 4)
            s += kr[j] * qr[j];
        s += __shfl_down_sync(0xffffffffu, s, 2);
        s += __shfl_down_sync(0xffffffffu, s, 1);
        if (ql == 0) {
            if (mask[b * 32 + n] != 0) s = -1e10f;
            sc[g] = s;
        }
    }
    __syncthreads();

    const int wid  = tid >> 5;
    const int lane = tid & 31;
    if (wid < 2) {
        float s = sc[wid * 32 + lane];
        float m = s;
#pragma unroll
        for (int o = 16; o > 0; o >>= 1)
            m = fmaxf(m, __shfl_xor_sync(0xffffffffu, m, o));
        float e = expf(s - m);
        float sum = e;
#pragma unroll
        for (int o = 16; o > 0; o >>= 1)
            sum += __shfl_xor_sync(0xffffffffu, sum, o);
        float p = e / sum;
        at[wid * 32 + lane] = p;
        attn_out[((size_t)wid * B_ + b) * 32 + lane] = p;
    }
    __syncthreads();

    for (int c = tid; c < 768; c += 256) {
        int h = (c >= 384) ? 1 : 0;
        int j = c - h * 384;
        const float* av = at + h * 32;
        float accv = 0.f;
#pragma unroll
        for (int n = 0; n < 32; n++)
            accv += av[n] * kbuf[n * KSTRIDE + j];
        Cbuf[(size_t)b * 768 + c] = accv;
    }
}

// ---------------------------------------------------------------------------
// In-place LayerNorm over rows of 384 (one warp per row)
// ---------------------------------------------------------------------------
__global__ __launch_bounds__(256) void ln_kernel(
    float* __restrict__ Y,
    const float* __restrict__ ln_g,
    const float* __restrict__ ln_b)
{
    const int row  = blockIdx.x * 8 + (threadIdx.x >> 5);
    const int lane = threadIdx.x & 31;
    float* y = Y + (size_t)row * 384;

    float v[12];
    float s = 0.f;
#pragma unroll
    for (int i = 0; i < 12; i++) { v[i] = y[lane + i * 32]; s += v[i]; }
#pragma unroll
    for (int o = 16; o > 0; o >>= 1) s += __shfl_xor_sync(0xffffffffu, s, o);
    float mu = s * (1.f / 384.f);

    float q = 0.f;
#pragma unroll
    for (int i = 0; i < 12; i++) { float d = v[i] - mu; q += d * d; }
#pragma unroll
    for (int o = 16; o > 0; o >>= 1) q += __shfl_xor_sync(0xffffffffu, q, o);
    float inv = rsqrtf(q * (1.f / 384.f) + 1e-5f);

#pragma unroll
    for (int i = 0; i < 12; i++) {
        int c = lane + i * 32;
        y[c] = (v[i] - mu) * inv * ln_g[c] + ln_b[c];
    }
}

// ---------------------------------------------------------------------------
// Launch
// ---------------------------------------------------------------------------
extern "C" void kernel_launch(void* const* d_in, const int* in_sizes, int n_in,
                              void* d_out, int out_size)
{
    const float* src   = (const float*)d_in[0];
    const float* src_t = (const float*)d_in[1];
    const float* seq   = (const float*)d_in[2];
    const float* seq_t = (const float*)d_in[3];
    const float* seq_e = (const float*)d_in[4];
    const int*   mask  = (const int*)d_in[6];
    const float* w_q   = (const float*)d_in[7];
    const float* w_k   = (const float*)d_in[8];
    const float* w_v   = (const float*)d_in[9];
    const float* fc_w  = (const float*)d_in[10];
    const float* fc_b  = (const float*)d_in[11];
    const float* ln_g  = (const float*)d_in[12];
    const float* ln_b  = (const float*)d_in[13];
    const float* mg_w1 = (const float*)d_in[14];
    const float* mg_b1 = (const float*)d_in[15];
    const float* mg_w2 = (const float*)d_in[16];
    const float* mg_b2 = (const float*)d_in[17];
    float* out = (float*)d_out;
    float* merged_out = out;
    float* attn_out   = out + (size_t)B_ * D_;

    float *Tq, *Tk, *Tv, *Ahat, *Bhat, *Qt, *Cb, *Y, *Hb;
    cudaGetSymbolAddress((void**)&Tq,   g_Tq);
    cudaGetSymbolAddress((void**)&Tk,   g_Tk);
    cudaGetSymbolAddress((void**)&Tv,   g_Tv);
    cudaGetSymbolAddress((void**)&Ahat, g_Ahat);
    cudaGetSymbolAddress((void**)&Bhat, g_Bhat);
    cudaGetSymbolAddress((void**)&Qt,   g_Qt);
    cudaGetSymbolAddress((void**)&Cb,   g_C);
    cudaGetSymbolAddress((void**)&Y,    g_Y);
    cudaGetSymbolAddress((void**)&Hb,   g_H);

    const int ATTN_SMEM = (32 * KSTRIDE + 768 + 64 + 64) * (int)sizeof(float);
    cudaFuncSetAttribute(attn_kernel, cudaFuncAttributeMaxDynamicSharedMemorySize, ATTN_SMEM);

    dim3 tb(32, 8);
    transpose_head<<<dim3(256 / 32, 6, 2), tb>>>(w_q, Tq, 256, 128, 128);
    transpose_head<<<dim3(384 / 32, 6, 2), tb>>>(w_k, Tk, 384, 384, 0);
    transpose_head<<<dim3(384 / 32, 6, 2), tb>>>(w_v, Tv, 384, 384, 0);

    const float invs = (float)(1.0 / sqrt((double)DK_));

    // Ahat (both heads, z-batched): M=384, N=256, K=192
    mma_gemm<<<dim3(4, 3, 2), 256>>>(
        Tk, Tk, BIGK, 192, 192,
        Tq, 192, nullptr,
        Ahat, 256, 192, invs, 0,
        (size_t)384 * 192, (size_t)256 * 192, (size_t)384 * 256);

    // Bhat (both heads, z-batched): M=384, N=384, K=192
    mma_gemm<<<dim3(6, 3, 2), 256>>>(
        fc_w, fc_w, BIGK, 384, 384,
        Tv, 192, nullptr,
        Bhat, 768, 192, 1.f, 0,
        (size_t)192, (size_t)384 * 192, (size_t)384);

    // Qt = [src | src_t] @ Ahat^T   (8192 x 768, K=256)
    mma_gemm<<<dim3(12, 64, 1), 256>>>(
        src, src_t, 128, 128, 128,
        Ahat, 256, nullptr, Qt, 768, 256, 1.f, 0, 0, 0, 0);

    // Fused attention -> Cb and attn_w output
    attn_kernel<<<B_, 256, ATTN_SMEM>>>(Qt, seq, seq_e, seq_t, mask, Cb, attn_out);

    // Y = Cb @ Bhat^T + fc_b   (8192 x 384, K=768)
    mma_gemm<<<dim3(6, 64, 1), 256>>>(
        Cb, Cb, BIGK, 768, 768,
        Bhat, 768, fc_b, Y, 384, 768, 1.f, 0, 0, 0, 0);

    // LayerNorm in place
    ln_kernel<<<B_ / 8, 256>>>(Y, ln_g, ln_b);

    // Hb = relu([Y | src] @ mg_w1^T + mg_b1)   (8192 x 128, K=512)
    mma_gemm<<<dim3(2, 64, 1), 256>>>(
        Y, src, 384, 384, 128,
        mg_w1, 512, mg_b1, Hb, 128, 512, 1.f, 1, 0, 0, 0);

    // merged = Hb @ mg_w2^T + mg_b2   (8192 x 128, K=128)
    mma_gemm<<<dim3(2, 64, 1), 256>>>(
        Hb, Hb, BIGK, 128, 128,
        mg_w2, 128, mg_b2, merged_out, 128, 128, 1.f, 0, 0, 0, 0);

    (void)in_sizes; (void)n_in; (void)out_size; (void)seq_t;
}